// round 10
// baseline (speedup 1.0000x reference)
#include <cuda_runtime.h>
#include <math.h>

#define NROWS (64*9*374)      // 215424 rows of F=128
#define BT    (64*9)          // 576 (b,t) groups
#define RR    374
#define KSEL  299
#define NBLK1 (NROWS/64)      // 3366 k1 blocks (64 rows each, exact)
#define EPS_TINY 1.17549435082228750797e-38f

typedef unsigned long long u64;

// scratch (static device memory — no runtime allocation)
__device__ __align__(16) float g_acc32[(size_t)NROWS*32]; // local @ w2[:64]
__device__ float g_part[NBLK1*128];                       // per-block hi partials
__device__ float g_gcon[BT*32];                           // glob @ w2[64:,:]
__device__ float g_scores[NROWS];                         // score + gumbel

__device__ __forceinline__ u64 fma2(u64 a, u64 b, u64 c) {
    u64 d; asm("fma.rn.f32x2 %0,%1,%2,%3;" : "=l"(d) : "l"(a), "l"(b), "l"(c));
    return d;
}
__device__ __forceinline__ u64 pk2(float lo, float hi) {
    u64 r; asm("mov.b64 %0,{%1,%2};" : "=l"(r) : "f"(lo), "f"(hi));
    return r;
}
__device__ __forceinline__ void upk2(u64 v, float& lo, float& hi) {
    asm("mov.b64 {%0,%1},%2;" : "=f"(lo), "=f"(hi) : "l"(v));
}
__device__ __forceinline__ float frcp(float x) {
    float r; asm("rcp.approx.ftz.f32 %0,%1;" : "=f"(r) : "f"(x));
    return r;
}
__device__ __forceinline__ float warp_sum(float v) {
    #pragma unroll
    for (int o = 16; o; o >>= 1) v += __shfl_xor_sync(0xffffffffu, v, o);
    return v;
}
__device__ __forceinline__ float gelu_exact(float x) {
    return 0.5f * x * (1.0f + erff(x * 0.70710678118654752440f));
}

// ---------------------------------------------------------------------------
// Kernel 1: LayerNorm + GEMM1 (64x128 tile, K=128) + GELU + fused stage-2
// GEMM (gelu_local[64x64] @ w2[:64,:32]) + glob partials.
// 256 threads, 2 blocks/SM. f32x2 paired over COLUMNS, 4-k inner steps:
// a = LDS.128 (4 k per load, warp-broadcast), b = LDS.128 conflict-free.
// Crossbar: 20 phases per 64 FFMA2 per warp (62% of FMA2 pipe) -> FFMA2-bound.
// ---------------------------------------------------------------------------
__global__ void __launch_bounds__(256, 2) k1_ln_gemm1(
    const float* __restrict__ x, const float* __restrict__ ln_w,
    const float* __restrict__ ln_b, const float* __restrict__ w1,
    const float* __restrict__ b1, const float* __restrict__ w2)
{
    extern __shared__ float sm[];
    float* w1s = sm;                      // [128 k][132]  (k-major)
    float* xs  = sm + 128*132;            // [64 rows][132]
    float* red = sm + 128*132 + 64*132;   // [2][64][17]
    float* hlocal = sm;                   // [64 rows][68]   (reuses w1s)
    float* w2t    = sm + 64*68;           // [32 cols][66]   (reuses w1s)

    const int t  = threadIdx.x;
    const int R0 = blockIdx.x * 64;

    // stage w1 k-major (coalesced float4 both sides)
    #pragma unroll
    for (int i = 0; i < 16; i++) {
        int id = i*256 + t;              // k = id/32, c4 = (id%32)*4
        int k  = id >> 5, c4 = (id & 31) << 2;
        float4 v = ((const float4*)w1)[id];
        *(float4*)(w1s + k*132 + c4) = v;
    }

    // layernorm: 8 warps x 8 rows
    {
        const int lane = t & 31, w = t >> 5;
        float4 lw = ((const float4*)ln_w)[lane];
        float4 lb = ((const float4*)ln_b)[lane];
        #pragma unroll
        for (int rr = 0; rr < 8; rr++) {
            int r = w*8 + rr;
            float4 xv = ((const float4*)x)[(size_t)(R0 + r)*32 + lane];
            float s = warp_sum(xv.x + xv.y + xv.z + xv.w);
            float m = s * (1.0f/128.0f);
            float dx = xv.x - m, dy = xv.y - m, dz = xv.z - m, dw = xv.w - m;
            float q = warp_sum(dx*dx + dy*dy + dz*dz + dw*dw);
            float rs = rsqrtf(q * (1.0f/128.0f) + 1e-5f);
            float4 y;
            y.x = dx*rs*lw.x + lb.x;
            y.y = dy*rs*lw.y + lb.y;
            y.z = dz*rs*lw.z + lb.z;
            y.w = dw*rs*lw.w + lb.w;
            *(float4*)(xs + r*132 + lane*4) = y;
        }
    }
    __syncthreads();

    const int ty = t >> 4, tx = t & 15;   // rows 4ty..4ty+3, cols 4tx+{0..3,64..67}
    float part[2][4];
    {
        u64 acc[4][4];                    // [row][quad]: 0,1 local; 2,3 hi
        #pragma unroll
        for (int i = 0; i < 4; i++)
            #pragma unroll
            for (int j = 0; j < 4; j++) acc[i][j] = 0ULL;

        #pragma unroll 2
        for (int kq = 0; kq < 32; kq++) { // 4 k per iteration
            int k = kq*4;
            float4 af[4];
            #pragma unroll
            for (int i = 0; i < 4; i++)
                af[i] = *(const float4*)(xs + (ty*4 + i)*132 + k);
            #pragma unroll
            for (int kk = 0; kk < 4; kk++) {
                float4 bl = *(const float4*)(w1s + (k + kk)*132 + tx*4);
                float4 bh = *(const float4*)(w1s + (k + kk)*132 + tx*4 + 64);
                u64 l0 = ((const u64*)&bl)[0], l1 = ((const u64*)&bl)[1];
                u64 h0 = ((const u64*)&bh)[0], h1 = ((const u64*)&bh)[1];
                #pragma unroll
                for (int i = 0; i < 4; i++) {
                    float xv = (&af[i].x)[kk];
                    u64 a = pk2(xv, xv);
                    acc[i][0] = fma2(a, l0, acc[i][0]);
                    acc[i][1] = fma2(a, l1, acc[i][1]);
                    acc[i][2] = fma2(a, h0, acc[i][2]);
                    acc[i][3] = fma2(a, h1, acc[i][3]);
                }
            }
        }
        __syncthreads();   // done reading w1s/xs; w1s region reusable

        float4 bl = *(const float4*)(b1 + tx*4);
        float4 bh = *(const float4*)(b1 + tx*4 + 64);

        const int g0 = R0 / RR;
        const int boundary = (g0 + 1) * RR;
        #pragma unroll
        for (int sdd = 0; sdd < 2; sdd++)
            #pragma unroll
            for (int j = 0; j < 4; j++) part[sdd][j] = 0.0f;

        #pragma unroll
        for (int i = 0; i < 4; i++) {
            int rg = R0 + ty*4 + i;
            int rl = ty*4 + i;
            // local half -> hlocal smem (float4, stride 68 = 16B multiple)
            float4 hv;
            float lo, hi;
            upk2(acc[i][0], lo, hi); hv.x = gelu_exact(lo + bl.x); hv.y = gelu_exact(hi + bl.y);
            upk2(acc[i][1], lo, hi); hv.z = gelu_exact(lo + bl.z); hv.w = gelu_exact(hi + bl.w);
            *(float4*)(hlocal + rl*68 + tx*4) = hv;
            // hi half -> glob partials
            int sd = (rg >= boundary) ? 1 : 0;
            float v0, v1, v2, v3;
            upk2(acc[i][2], lo, hi); v0 = gelu_exact(lo + bh.x); v1 = gelu_exact(hi + bh.y);
            upk2(acc[i][3], lo, hi); v2 = gelu_exact(lo + bh.z); v3 = gelu_exact(hi + bh.w);
            if (sd) { part[1][0]+=v0; part[1][1]+=v1; part[1][2]+=v2; part[1][3]+=v3; }
            else    { part[0][0]+=v0; part[0][1]+=v1; part[0][2]+=v2; part[0][3]+=v3; }
        }
    }

    // red[side][col][ty], stride 17
    #pragma unroll
    for (int sdd = 0; sdd < 2; sdd++)
        #pragma unroll
        for (int j = 0; j < 4; j++)
            red[(sdd*64 + tx*4 + j)*17 + ty] = part[sdd][j];

    // stage transposed w2[:64,:32] into w2t (after w1s freed)
    #pragma unroll
    for (int i = 0; i < 8; i++) {
        int id = i*256 + t;              // k = id/32, c = id%32
        int k = id >> 5, c = id & 31;
        w2t[c*66 + k] = w2[id];
    }
    __syncthreads();

    // glob partial reduce -> g_part
    if (t < 128) {
        const float* rp = red + t*17;
        float s = 0.0f;
        #pragma unroll
        for (int i = 0; i < 16; i++) s += rp[i];
        g_part[blockIdx.x*128 + t] = s;
    }

    // stage-2 GEMM: hlocal[64x64] @ w2t -> g_acc32 (cols tx, tx+16), K paired
    {
        u64 acc2[4][2];
        #pragma unroll
        for (int i = 0; i < 4; i++) { acc2[i][0] = 0ULL; acc2[i][1] = 0ULL; }

        const u64* hu   = (const u64*)hlocal;           // row stride 34 u64
        const u64* w2u0 = (const u64*)(w2t + tx*66);
        const u64* w2u1 = (const u64*)(w2t + (tx+16)*66);
        #pragma unroll 8
        for (int k2 = 0; k2 < 32; k2++) {
            u64 b0 = w2u0[k2], b1v = w2u1[k2];
            #pragma unroll
            for (int i = 0; i < 4; i++) {
                u64 a = hu[(ty*4 + i)*34 + k2];
                acc2[i][0] = fma2(a, b0,  acc2[i][0]);
                acc2[i][1] = fma2(a, b1v, acc2[i][1]);
            }
        }
        #pragma unroll
        for (int i = 0; i < 4; i++) {
            size_t rg = (size_t)(R0 + ty*4 + i);
            float lo, hi;
            upk2(acc2[i][0], lo, hi);
            g_acc32[rg*32 + tx]      = lo + hi;
            upk2(acc2[i][1], lo, hi);
            g_acc32[rg*32 + tx + 16] = lo + hi;
        }
    }
}

// ---------------------------------------------------------------------------
// Kernel glob: combine per-block partials -> mean -> glob @ w2[64:,:].
// ---------------------------------------------------------------------------
__global__ void __launch_bounds__(64) k_glob(const float* __restrict__ w2)
{
    __shared__ float gl[64];
    const int g = blockIdx.x, c = threadIdx.x;
    const int b_start = (g * RR) >> 6;
    const int b_end   = (g * RR + RR - 1) >> 6;
    float s = 0.0f;
    for (int b = b_start; b <= b_end; b++) {
        int side = g - (b * 64) / RR;     // 0 or 1 by construction
        s += g_part[b*128 + side*64 + c];
    }
    gl[c] = s * (1.0f/374.0f);
    __syncthreads();
    if (c < 32) {
        float a = 0.0f;
        #pragma unroll
        for (int k = 0; k < 64; k++) a += gl[k] * w2[(64 + k)*32 + c];
        g_gcon[g*32 + c] = a;
    }
}

// ---------------------------------------------------------------------------
// Kernel 2 (elementwise): gelu(acc32 + gcon + b2) -> w3 head -> softmax ->
// score + Gumbel -> g_scores.
// ---------------------------------------------------------------------------
__global__ void __launch_bounds__(256) k2_scores(
    const float* __restrict__ b2, const float* __restrict__ w3,
    const float* __restrict__ b3, const float* __restrict__ u)
{
    __shared__ float b2s[32];
    __shared__ float w3s[64];
    __shared__ float b3s[2];
    const int t = threadIdx.x;
    if (t < 32) b2s[t] = b2[t];
    if (t < 64) w3s[t] = w3[t];
    if (t < 2)  b3s[t] = b3[t];
    __syncthreads();

    const int e = blockIdx.x*256 + t;
    if (e >= NROWS) return;
    const int bt = e / RR;
    const float* gc = g_gcon + bt*32;

    float z0 = b3s[0], z1 = b3s[1];
    const float4* ap = (const float4*)(g_acc32 + (size_t)e*32);
    #pragma unroll
    for (int q = 0; q < 8; q++) {
        float4 a = ap[q];
        int c = q*4;
        float h0 = gelu_exact(a.x + b2s[c]   + gc[c]);
        float h1 = gelu_exact(a.y + b2s[c+1] + gc[c+1]);
        float h2 = gelu_exact(a.z + b2s[c+2] + gc[c+2]);
        float h3 = gelu_exact(a.w + b2s[c+3] + gc[c+3]);
        z0 += h0*w3s[2*c]   + h1*w3s[2*c+2] + h2*w3s[2*c+4] + h3*w3s[2*c+6];
        z1 += h0*w3s[2*c+1] + h1*w3s[2*c+3] + h2*w3s[2*c+5] + h3*w3s[2*c+7];
    }
    float m  = fmaxf(z0, z1);
    float e0 = expf(z0 - m), e1 = expf(z1 - m);
    float score = e1 / (e0 + e1);
    float uu  = u[e];
    float gum = -logf(-logf(uu));
    g_scores[e] = score + gum;
}

// ---------------------------------------------------------------------------
// Kernel 3: 299-step subset-operator scan, one warp per (b,t).
// Slim multiplicative loop + rcp.approx; SHFL butterfly reduction.
// ---------------------------------------------------------------------------
__global__ void __launch_bounds__(32) k3_scan(float* __restrict__ out)
{
    const int bt = blockIdx.x, lane = threadIdx.x;

    float ex[12], kh[12];
    #pragma unroll
    for (int j = 0; j < 12; j++) {
        int idx = j*32 + lane;
        ex[j] = (idx < RR) ? expf(g_scores[(size_t)bt*RR + idx]) : 0.0f;
        kh[j] = 0.0f;
    }

    #pragma unroll 1
    for (int it = 0; it < KSEL - 1; it++) {
        float z = (((ex[0] + ex[1]) + (ex[2] + ex[3])) +
                   ((ex[4] + ex[5]) + (ex[6] + ex[7]))) +
                  ((ex[8] + ex[9]) + (ex[10] + ex[11]));
        #pragma unroll
        for (int o = 16; o; o >>= 1) z += __shfl_xor_sync(0xffffffffu, z, o);
        float rinv = frcp(z);
        #pragma unroll
        for (int j = 0; j < 12; j++) {
            kh[j] = fmaf(ex[j], rinv, kh[j]);
            float m = fmaxf(fmaf(-ex[j], rinv, 1.0f), EPS_TINY);
            ex[j] *= m;
        }
    }
    {
        float z = (((ex[0] + ex[1]) + (ex[2] + ex[3])) +
                   ((ex[4] + ex[5]) + (ex[6] + ex[7]))) +
                  ((ex[8] + ex[9]) + (ex[10] + ex[11]));
        #pragma unroll
        for (int o = 16; o; o >>= 1) z += __shfl_xor_sync(0xffffffffu, z, o);
        float rinv = frcp(z);
        #pragma unroll
        for (int j = 0; j < 12; j++) kh[j] = fmaf(ex[j], rinv, kh[j]);
    }

    #pragma unroll
    for (int j = 0; j < 12; j++) {
        int idx = j*32 + lane;
        if (idx < RR) out[(size_t)bt*RR + idx] = kh[j];
    }
}

// ---------------------------------------------------------------------------
// Kernel 4: stable top-K rank (value desc, ties -> lower index).
// ---------------------------------------------------------------------------
__global__ void __launch_bounds__(384) k4_rank(float* __restrict__ out)
{
    __shared__ float ks[RR];
    const int bt = blockIdx.x, t = threadIdx.x;
    if (t < RR) ks[t] = out[(size_t)bt*RR + t];
    __syncthreads();
    if (t >= RR) return;
    const float mine = ks[t];
    int rank = 0;
    #pragma unroll 4
    for (int i = 0; i < RR; i++) {
        float kv = ks[i];
        rank += (kv > mine) || (kv == mine && i < t);
    }
    if (rank < KSEL)
        out[(size_t)NROWS + (size_t)bt*KSEL + rank] = (float)t;
}

// ---------------------------------------------------------------------------
extern "C" void kernel_launch(void* const* d_in, const int* in_sizes, int n_in,
                              void* d_out, int out_size)
{
    const float* x   = (const float*)d_in[0];
    const float* u   = (const float*)d_in[1];
    const float* lnw = (const float*)d_in[2];
    const float* lnb = (const float*)d_in[3];
    const float* w1  = (const float*)d_in[4];
    const float* b1  = (const float*)d_in[5];
    const float* w2  = (const float*)d_in[6];
    const float* b2  = (const float*)d_in[7];
    const float* w3  = (const float*)d_in[8];
    const float* b3  = (const float*)d_in[9];
    float* out = (float*)d_out;

    // w1s 128*132 + xs 64*132 + red 2*64*17 = 27520 floats = 110080 B
    const size_t smem1 = (size_t)(128*132 + 64*132 + 2*64*17) * sizeof(float);
    cudaFuncSetAttribute(k1_ln_gemm1, cudaFuncAttributeMaxDynamicSharedMemorySize,
                         (int)smem1);

    k1_ln_gemm1<<<NBLK1, 256, smem1>>>(x, lnw, lnb, w1, b1, w2);
    k_glob<<<BT, 64>>>(w2);
    k2_scores<<<(NROWS + 255)/256, 256>>>(b2, w3, b3, u);
    k3_scan<<<BT, 32>>>(out);
    k4_rank<<<BT, 384>>>(out);
}

// round 11
// speedup vs baseline: 1.0218x; 1.0218x over previous
#include <cuda_runtime.h>
#include <math.h>

#define NROWS (64*9*374)      // 215424 rows of F=128
#define BT    (64*9)          // 576 (b,t) groups
#define RR    374
#define KSEL  299
#define NBLK1 (NROWS/64)      // 3366 k1 blocks (64 rows each, exact)
#define EPS_TINY 1.17549435082228750797e-38f

typedef unsigned long long u64;

// scratch (static device memory — no runtime allocation)
__device__ __align__(16) float g_acc32[(size_t)NROWS*32]; // local @ w2[:64]
__device__ float g_part[NBLK1*128];                       // per-block hi partials
__device__ float g_gcon[BT*32];                           // glob @ w2[64:,:]
__device__ float g_scores[NROWS];                         // score + gumbel

__device__ __forceinline__ u64 fma2(u64 a, u64 b, u64 c) {
    u64 d; asm("fma.rn.f32x2 %0,%1,%2,%3;" : "=l"(d) : "l"(a), "l"(b), "l"(c));
    return d;
}
__device__ __forceinline__ u64 pk2(float lo, float hi) {
    u64 r; asm("mov.b64 %0,{%1,%2};" : "=l"(r) : "f"(lo), "f"(hi));
    return r;
}
__device__ __forceinline__ void upk2(u64 v, float& lo, float& hi) {
    asm("mov.b64 {%0,%1},%2;" : "=f"(lo), "=f"(hi) : "l"(v));
}
__device__ __forceinline__ float frcp(float x) {
    float r; asm("rcp.approx.ftz.f32 %0,%1;" : "=f"(r) : "f"(x));
    return r;
}
__device__ __forceinline__ float warp_sum(float v) {
    #pragma unroll
    for (int o = 16; o; o >>= 1) v += __shfl_xor_sync(0xffffffffu, v, o);
    return v;
}
// Branchless exact-enough GELU: erf via Abramowitz-Stegun 7.1.26
// (max abs err ~1.5e-7 + ~1e-7 from rcp/expf approx). No divergence.
__device__ __forceinline__ float gelu_exact(float x) {
    float z = x * 0.70710678118654752440f;
    float s = fabsf(z);
    float t = frcp(fmaf(0.3275911f, s, 1.0f));
    float p = t * fmaf(t, fmaf(t, fmaf(t, fmaf(t, 1.061405429f, -1.453152027f),
                                       1.421413741f), -0.284496736f), 0.254829592f);
    float e = __expf(-s * s);
    float erf_abs = fmaf(-p, e, 1.0f);
    float er = copysignf(erf_abs, z);
    return 0.5f * x * (1.0f + er);
}

// ---------------------------------------------------------------------------
// Kernel 1: LayerNorm + GEMM1 (64x128 tile, K=128) + GELU + fused stage-2
// GEMM (gelu_local[64x64] @ w2[:64,:32]) + glob partials.
// 256 threads, 2 blocks/SM. f32x2 paired over COLUMNS, 4-k inner steps.
// ---------------------------------------------------------------------------
__global__ void __launch_bounds__(256, 2) k1_ln_gemm1(
    const float* __restrict__ x, const float* __restrict__ ln_w,
    const float* __restrict__ ln_b, const float* __restrict__ w1,
    const float* __restrict__ b1, const float* __restrict__ w2)
{
    extern __shared__ float sm[];
    float* w1s = sm;                      // [128 k][132]  (k-major)
    float* xs  = sm + 128*132;            // [64 rows][132]
    float* red = sm + 128*132 + 64*132;   // [2][64][17]
    float* hlocal = sm;                   // [64 rows][68]   (reuses w1s)
    float* w2t    = sm + 64*68;           // [32 cols][66]   (reuses w1s)

    const int t  = threadIdx.x;
    const int R0 = blockIdx.x * 64;

    // stage w1 k-major (coalesced float4 both sides)
    #pragma unroll
    for (int i = 0; i < 16; i++) {
        int id = i*256 + t;              // k = id/32, c4 = (id%32)*4
        int k  = id >> 5, c4 = (id & 31) << 2;
        float4 v = ((const float4*)w1)[id];
        *(float4*)(w1s + k*132 + c4) = v;
    }

    // layernorm: 8 warps x 8 rows
    {
        const int lane = t & 31, w = t >> 5;
        float4 lw = ((const float4*)ln_w)[lane];
        float4 lb = ((const float4*)ln_b)[lane];
        #pragma unroll
        for (int rr = 0; rr < 8; rr++) {
            int r = w*8 + rr;
            float4 xv = ((const float4*)x)[(size_t)(R0 + r)*32 + lane];
            float s = warp_sum(xv.x + xv.y + xv.z + xv.w);
            float m = s * (1.0f/128.0f);
            float dx = xv.x - m, dy = xv.y - m, dz = xv.z - m, dw = xv.w - m;
            float q = warp_sum(dx*dx + dy*dy + dz*dz + dw*dw);
            float rs = rsqrtf(q * (1.0f/128.0f) + 1e-5f);
            float4 y;
            y.x = dx*rs*lw.x + lb.x;
            y.y = dy*rs*lw.y + lb.y;
            y.z = dz*rs*lw.z + lb.z;
            y.w = dw*rs*lw.w + lb.w;
            *(float4*)(xs + r*132 + lane*4) = y;
        }
    }
    __syncthreads();

    const int ty = t >> 4, tx = t & 15;   // rows 4ty..4ty+3, cols 4tx+{0..3,64..67}
    float part[2][4];
    {
        u64 acc[4][4];                    // [row][quad]: 0,1 local; 2,3 hi
        #pragma unroll
        for (int i = 0; i < 4; i++)
            #pragma unroll
            for (int j = 0; j < 4; j++) acc[i][j] = 0ULL;

        #pragma unroll 2
        for (int kq = 0; kq < 32; kq++) { // 4 k per iteration
            int k = kq*4;
            float4 af[4];
            #pragma unroll
            for (int i = 0; i < 4; i++)
                af[i] = *(const float4*)(xs + (ty*4 + i)*132 + k);
            #pragma unroll
            for (int kk = 0; kk < 4; kk++) {
                float4 bl = *(const float4*)(w1s + (k + kk)*132 + tx*4);
                float4 bh = *(const float4*)(w1s + (k + kk)*132 + tx*4 + 64);
                u64 l0 = ((const u64*)&bl)[0], l1 = ((const u64*)&bl)[1];
                u64 h0 = ((const u64*)&bh)[0], h1 = ((const u64*)&bh)[1];
                #pragma unroll
                for (int i = 0; i < 4; i++) {
                    float xv = (&af[i].x)[kk];
                    u64 a = pk2(xv, xv);
                    acc[i][0] = fma2(a, l0, acc[i][0]);
                    acc[i][1] = fma2(a, l1, acc[i][1]);
                    acc[i][2] = fma2(a, h0, acc[i][2]);
                    acc[i][3] = fma2(a, h1, acc[i][3]);
                }
            }
        }
        __syncthreads();   // done reading w1s/xs; w1s region reusable

        float4 bl = *(const float4*)(b1 + tx*4);
        float4 bh = *(const float4*)(b1 + tx*4 + 64);

        const int g0 = R0 / RR;
        const int boundary = (g0 + 1) * RR;
        #pragma unroll
        for (int sdd = 0; sdd < 2; sdd++)
            #pragma unroll
            for (int j = 0; j < 4; j++) part[sdd][j] = 0.0f;

        #pragma unroll
        for (int i = 0; i < 4; i++) {
            int rg = R0 + ty*4 + i;
            int rl = ty*4 + i;
            // local half -> hlocal smem (float4, stride 68 = 16B multiple)
            float4 hv;
            float lo, hi;
            upk2(acc[i][0], lo, hi); hv.x = gelu_exact(lo + bl.x); hv.y = gelu_exact(hi + bl.y);
            upk2(acc[i][1], lo, hi); hv.z = gelu_exact(lo + bl.z); hv.w = gelu_exact(hi + bl.w);
            *(float4*)(hlocal + rl*68 + tx*4) = hv;
            // hi half -> glob partials
            int sd = (rg >= boundary) ? 1 : 0;
            float v0, v1, v2, v3;
            upk2(acc[i][2], lo, hi); v0 = gelu_exact(lo + bh.x); v1 = gelu_exact(hi + bh.y);
            upk2(acc[i][3], lo, hi); v2 = gelu_exact(lo + bh.z); v3 = gelu_exact(hi + bh.w);
            if (sd) { part[1][0]+=v0; part[1][1]+=v1; part[1][2]+=v2; part[1][3]+=v3; }
            else    { part[0][0]+=v0; part[0][1]+=v1; part[0][2]+=v2; part[0][3]+=v3; }
        }
    }

    // red[side][col][ty], stride 17
    #pragma unroll
    for (int sdd = 0; sdd < 2; sdd++)
        #pragma unroll
        for (int j = 0; j < 4; j++)
            red[(sdd*64 + tx*4 + j)*17 + ty] = part[sdd][j];

    // stage transposed w2[:64,:32] into w2t (after w1s freed)
    #pragma unroll
    for (int i = 0; i < 8; i++) {
        int id = i*256 + t;              // k = id/32, c = id%32
        int k = id >> 5, c = id & 31;
        w2t[c*66 + k] = w2[id];
    }
    __syncthreads();

    // glob partial reduce -> g_part
    if (t < 128) {
        const float* rp = red + t*17;
        float s = 0.0f;
        #pragma unroll
        for (int i = 0; i < 16; i++) s += rp[i];
        g_part[blockIdx.x*128 + t] = s;
    }

    // stage-2 GEMM: hlocal[64x64] @ w2t -> g_acc32 (cols tx, tx+16), K paired
    {
        u64 acc2[4][2];
        #pragma unroll
        for (int i = 0; i < 4; i++) { acc2[i][0] = 0ULL; acc2[i][1] = 0ULL; }

        const u64* hu   = (const u64*)hlocal;           // row stride 34 u64
        const u64* w2u0 = (const u64*)(w2t + tx*66);
        const u64* w2u1 = (const u64*)(w2t + (tx+16)*66);
        #pragma unroll 8
        for (int k2 = 0; k2 < 32; k2++) {
            u64 b0 = w2u0[k2], b1v = w2u1[k2];
            #pragma unroll
            for (int i = 0; i < 4; i++) {
                u64 a = hu[(ty*4 + i)*34 + k2];
                acc2[i][0] = fma2(a, b0,  acc2[i][0]);
                acc2[i][1] = fma2(a, b1v, acc2[i][1]);
            }
        }
        #pragma unroll
        for (int i = 0; i < 4; i++) {
            size_t rg = (size_t)(R0 + ty*4 + i);
            float lo, hi;
            upk2(acc2[i][0], lo, hi);
            g_acc32[rg*32 + tx]      = lo + hi;
            upk2(acc2[i][1], lo, hi);
            g_acc32[rg*32 + tx + 16] = lo + hi;
        }
    }
}

// ---------------------------------------------------------------------------
// Kernel glob: combine per-block partials -> mean -> glob @ w2[64:,:].
// ---------------------------------------------------------------------------
__global__ void __launch_bounds__(64) k_glob(const float* __restrict__ w2)
{
    __shared__ float gl[64];
    const int g = blockIdx.x, c = threadIdx.x;
    const int b_start = (g * RR) >> 6;
    const int b_end   = (g * RR + RR - 1) >> 6;
    float s = 0.0f;
    for (int b = b_start; b <= b_end; b++) {
        int side = g - (b * 64) / RR;     // 0 or 1 by construction
        s += g_part[b*128 + side*64 + c];
    }
    gl[c] = s * (1.0f/374.0f);
    __syncthreads();
    if (c < 32) {
        float a = 0.0f;
        #pragma unroll
        for (int k = 0; k < 64; k++) a += gl[k] * w2[(64 + k)*32 + c];
        g_gcon[g*32 + c] = a;
    }
}

// ---------------------------------------------------------------------------
// Kernel 2 (elementwise): gelu(acc32 + gcon + b2) -> w3 head -> softmax ->
// score + Gumbel -> g_scores.
// ---------------------------------------------------------------------------
__global__ void __launch_bounds__(256) k2_scores(
    const float* __restrict__ b2, const float* __restrict__ w3,
    const float* __restrict__ b3, const float* __restrict__ u)
{
    __shared__ float b2s[32];
    __shared__ float w3s[64];
    __shared__ float b3s[2];
    const int t = threadIdx.x;
    if (t < 32) b2s[t] = b2[t];
    if (t < 64) w3s[t] = w3[t];
    if (t < 2)  b3s[t] = b3[t];
    __syncthreads();

    const int e = blockIdx.x*256 + t;
    if (e >= NROWS) return;
    const int bt = e / RR;
    const float* gc = g_gcon + bt*32;

    float z0 = b3s[0], z1 = b3s[1];
    const float4* ap = (const float4*)(g_acc32 + (size_t)e*32);
    #pragma unroll
    for (int q = 0; q < 8; q++) {
        float4 a = ap[q];
        int c = q*4;
        float h0 = gelu_exact(a.x + b2s[c]   + gc[c]);
        float h1 = gelu_exact(a.y + b2s[c+1] + gc[c+1]);
        float h2 = gelu_exact(a.z + b2s[c+2] + gc[c+2]);
        float h3 = gelu_exact(a.w + b2s[c+3] + gc[c+3]);
        z0 += h0*w3s[2*c]   + h1*w3s[2*c+2] + h2*w3s[2*c+4] + h3*w3s[2*c+6];
        z1 += h0*w3s[2*c+1] + h1*w3s[2*c+3] + h2*w3s[2*c+5] + h3*w3s[2*c+7];
    }
    float m  = fmaxf(z0, z1);
    float e0 = expf(z0 - m), e1 = expf(z1 - m);
    float score = e1 / (e0 + e1);
    float uu  = u[e];
    float gum = -logf(-logf(uu));
    g_scores[e] = score + gum;
}

// ---------------------------------------------------------------------------
// Kernel 3: 299-step subset-operator scan, one warp per (b,t).
// Slim multiplicative loop + rcp.approx; SHFL butterfly reduction.
// ---------------------------------------------------------------------------
__global__ void __launch_bounds__(32) k3_scan(float* __restrict__ out)
{
    const int bt = blockIdx.x, lane = threadIdx.x;

    float ex[12], kh[12];
    #pragma unroll
    for (int j = 0; j < 12; j++) {
        int idx = j*32 + lane;
        ex[j] = (idx < RR) ? expf(g_scores[(size_t)bt*RR + idx]) : 0.0f;
        kh[j] = 0.0f;
    }

    #pragma unroll 1
    for (int it = 0; it < KSEL - 1; it++) {
        float z = (((ex[0] + ex[1]) + (ex[2] + ex[3])) +
                   ((ex[4] + ex[5]) + (ex[6] + ex[7]))) +
                  ((ex[8] + ex[9]) + (ex[10] + ex[11]));
        #pragma unroll
        for (int o = 16; o; o >>= 1) z += __shfl_xor_sync(0xffffffffu, z, o);
        float rinv = frcp(z);
        #pragma unroll
        for (int j = 0; j < 12; j++) {
            kh[j] = fmaf(ex[j], rinv, kh[j]);
            float m = fmaxf(fmaf(-ex[j], rinv, 1.0f), EPS_TINY);
            ex[j] *= m;
        }
    }
    {
        float z = (((ex[0] + ex[1]) + (ex[2] + ex[3])) +
                   ((ex[4] + ex[5]) + (ex[6] + ex[7]))) +
                  ((ex[8] + ex[9]) + (ex[10] + ex[11]));
        #pragma unroll
        for (int o = 16; o; o >>= 1) z += __shfl_xor_sync(0xffffffffu, z, o);
        float rinv = frcp(z);
        #pragma unroll
        for (int j = 0; j < 12; j++) kh[j] = fmaf(ex[j], rinv, kh[j]);
    }

    #pragma unroll
    for (int j = 0; j < 12; j++) {
        int idx = j*32 + lane;
        if (idx < RR) out[(size_t)bt*RR + idx] = kh[j];
    }
}

// ---------------------------------------------------------------------------
// Kernel 4: stable top-K rank (value desc, ties -> lower index).
// ---------------------------------------------------------------------------
__global__ void __launch_bounds__(384) k4_rank(float* __restrict__ out)
{
    __shared__ float ks[RR];
    const int bt = blockIdx.x, t = threadIdx.x;
    if (t < RR) ks[t] = out[(size_t)bt*RR + t];
    __syncthreads();
    if (t >= RR) return;
    const float mine = ks[t];
    int rank = 0;
    #pragma unroll 4
    for (int i = 0; i < RR; i++) {
        float kv = ks[i];
        rank += (kv > mine) || (kv == mine && i < t);
    }
    if (rank < KSEL)
        out[(size_t)NROWS + (size_t)bt*KSEL + rank] = (float)t;
}

// ---------------------------------------------------------------------------
extern "C" void kernel_launch(void* const* d_in, const int* in_sizes, int n_in,
                              void* d_out, int out_size)
{
    const float* x   = (const float*)d_in[0];
    const float* u   = (const float*)d_in[1];
    const float* lnw = (const float*)d_in[2];
    const float* lnb = (const float*)d_in[3];
    const float* w1  = (const float*)d_in[4];
    const float* b1  = (const float*)d_in[5];
    const float* w2  = (const float*)d_in[6];
    const float* b2  = (const float*)d_in[7];
    const float* w3  = (const float*)d_in[8];
    const float* b3  = (const float*)d_in[9];
    float* out = (float*)d_out;

    // w1s 128*132 + xs 64*132 + red 2*64*17 = 27520 floats = 110080 B
    const size_t smem1 = (size_t)(128*132 + 64*132 + 2*64*17) * sizeof(float);
    cudaFuncSetAttribute(k1_ln_gemm1, cudaFuncAttributeMaxDynamicSharedMemorySize,
                         (int)smem1);

    k1_ln_gemm1<<<NBLK1, 256, smem1>>>(x, lnw, lnb, w1, b1, w2);
    k_glob<<<BT, 64>>>(w2);
    k2_scores<<<(NROWS + 255)/256, 256>>>(b2, w3, b3, u);
    k3_scan<<<BT, 32>>>(out);
    k4_rank<<<BT, 384>>>(out);
}